// round 7
// baseline (speedup 1.0000x reference)
#include <cuda_runtime.h>
#include <cuda_bf16.h>

// Problem constants
#define B_   4
#define CIN  64
#define C_   256
#define N_   1729          // 1 cls + 12*12*12 tokens
#define P_   1728
#define NH   8
#define HD   32
#define DEPTH 2
#define M_TOK (B_ * N_)    // 6916
#define KC   4             // key-split chunks
#define KCH  448           // keys per chunk (7 tiles of 64)

typedef unsigned long long ull;

// ---- packed f32x2 helpers (Blackwell FFMA2 path) ----
__device__ __forceinline__ ull pack2(float lo, float hi) {
    ull r; asm("mov.b64 %0, {%1, %2};" : "=l"(r) : "f"(lo), "f"(hi)); return r;
}
__device__ __forceinline__ void unpack2(ull v, float& lo, float& hi) {
    asm("mov.b64 {%0, %1}, %2;" : "=f"(lo), "=f"(hi) : "l"(v));
}
__device__ __forceinline__ void fma2(ull& d, ull a, ull b) {
    asm("fma.rn.f32x2 %0, %1, %2, %0;" : "+l"(d) : "l"(a), "l"(b));
}
__device__ __forceinline__ float hsum2x2(ull a, ull b) {
    float x0, x1, y0, y1;
    unpack2(a, x0, x1); unpack2(b, y0, y1);
    return (x0 + x1) + (y0 + y1);
}

// Scratch (device globals; no cudaMalloc allowed)
__device__ float g_t  [M_TOK * C_];
__device__ float g_y  [M_TOK * C_];
__device__ float g_qkv[M_TOK * 3 * C_];
__device__ float g_o  [M_TOK * C_];
__device__ float g_h  [M_TOK * C_];
__device__ float g_opart[KC * M_TOK * C_];          // unnormalized partial o
__device__ float g_lpart[KC * B_ * NH * N_];        // partial softmax sums

// ---------------------------------------------------------------------------
// Patch embed + cls token
// ---------------------------------------------------------------------------
__global__ void embed_kernel(const float* __restrict__ x,
                             const float* __restrict__ W_pe,
                             const float* __restrict__ b_pe,
                             const float* __restrict__ cls) {
    int n = blockIdx.x;
    int b = blockIdx.y;
    int d = threadIdx.x;
    if (n == 0) {
        g_t[(b * N_) * C_ + d] = cls[d];
        return;
    }
    int p = n - 1;
    __shared__ float sx[CIN];
    if (d < CIN) sx[d] = x[(b * CIN + d) * P_ + p];
    __syncthreads();
    float acc = b_pe[d];
#pragma unroll
    for (int c = 0; c < CIN; c++) acc += sx[c] * W_pe[c * C_ + d];
    g_t[(b * N_ + n) * C_ + d] = acc;
}

// ---------------------------------------------------------------------------
// LayerNorm (256 threads per token row)
// ---------------------------------------------------------------------------
__device__ __forceinline__ float ln_value(const float* __restrict__ in, int row, int tid,
                                          const float* __restrict__ g,
                                          const float* __restrict__ bb) {
    float v = in[row * C_ + tid];
    float s = v, sq = v * v;
#pragma unroll
    for (int o = 16; o > 0; o >>= 1) {
        s  += __shfl_down_sync(0xffffffffu, s,  o);
        sq += __shfl_down_sync(0xffffffffu, sq, o);
    }
    __shared__ float rs[8], rq[8];
    int wid = tid >> 5, lid = tid & 31;
    if (lid == 0) { rs[wid] = s; rq[wid] = sq; }
    __syncthreads();
    float sum = 0.f, sumq = 0.f;
#pragma unroll
    for (int i = 0; i < 8; i++) { sum += rs[i]; sumq += rq[i]; }
    float mean = sum * (1.f / C_);
    float var  = sumq * (1.f / C_) - mean * mean;
    float inv  = rsqrtf(var + 1e-5f);
    return (v - mean) * inv * g[tid] + bb[tid];
}

__global__ void ln_kernel(const float* __restrict__ in, float* __restrict__ out,
                          const float* __restrict__ g, const float* __restrict__ bb) {
    int row = blockIdx.x;
    int tid = threadIdx.x;
    out[row * C_ + tid] = ln_value(in, row, tid, g, bb);
}

__global__ void final_ln_kernel(const float* __restrict__ in,
                                const float* __restrict__ g, const float* __restrict__ bb,
                                float* __restrict__ out) {
    int row = blockIdx.x;
    int tid = threadIdx.x;
    float val = ln_value(in, row, tid, g, bb);
    int b = row / N_, n = row % N_;
    if (n == 0) out[b * C_ + tid] = val;
    else        out[B_ * C_ + (b * C_ + tid) * P_ + (n - 1)] = val;
}

// ---------------------------------------------------------------------------
// fp32 GEMM, 128x64 tile (for QKV, N=768). Per kk: 3 LDS.128 + 4 pack + 16 FFMA2.
// ---------------------------------------------------------------------------
template<bool GELU, bool RES>
__global__ __launch_bounds__(256) void gemm128(const float* __restrict__ A,
                                               const float* __restrict__ W,
                                               const float* __restrict__ bias,
                                               float* __restrict__ out,
                                               int M, int K, int N) {
    __shared__ float sA[16][132];
    __shared__ float sB[16][64];
    int tid = threadIdx.x;
    int tx = tid & 15;
    int ty = tid >> 4;
    int n0 = blockIdx.x * 64;
    int m0 = blockIdx.y * 128;

    ull acc[4][4];
#pragma unroll
    for (int i = 0; i < 4; i++)
#pragma unroll
        for (int j = 0; j < 4; j++) acc[i][j] = 0ull;

    for (int k0 = 0; k0 < K; k0 += 16) {
#pragma unroll
        for (int i = 0; i < 2; i++) {
            int idx = tid + i * 256;
            int ml  = idx >> 2;
            int q   = idx & 3;
            int m   = m0 + ml;
            float4 av = (m < M) ? *(const float4*)(A + (size_t)m * K + k0 + q * 4)
                                : make_float4(0.f, 0.f, 0.f, 0.f);
            sA[q * 4 + 0][ml] = av.x;
            sA[q * 4 + 1][ml] = av.y;
            sA[q * 4 + 2][ml] = av.z;
            sA[q * 4 + 3][ml] = av.w;
        }
        {
            int nl = (tid & 15) * 4;
            int kl = tid >> 4;
            *(float4*)&sB[kl][nl] = *(const float4*)(W + (size_t)(k0 + kl) * N + n0 + nl);
        }
        __syncthreads();

#pragma unroll
        for (int kk = 0; kk < 16; kk++) {
            ulonglong2 a01 = *(const ulonglong2*)&sA[kk][ty * 8];
            ulonglong2 a23 = *(const ulonglong2*)&sA[kk][ty * 8 + 4];
            float4 bf = *(const float4*)&sB[kk][tx * 4];
            ull ap[4] = {a01.x, a01.y, a23.x, a23.y};
            ull bp[4] = {pack2(bf.x, bf.x), pack2(bf.y, bf.y),
                         pack2(bf.z, bf.z), pack2(bf.w, bf.w)};
#pragma unroll
            for (int i = 0; i < 4; i++)
#pragma unroll
                for (int j = 0; j < 4; j++)
                    fma2(acc[i][j], ap[i], bp[j]);
        }
        __syncthreads();
    }

    float bv[4];
#pragma unroll
    for (int j = 0; j < 4; j++) bv[j] = bias ? bias[n0 + tx * 4 + j] : 0.f;

#pragma unroll
    for (int i = 0; i < 4; i++) {
        float vlo[4], vhi[4];
#pragma unroll
        for (int j = 0; j < 4; j++) unpack2(acc[i][j], vlo[j], vhi[j]);
#pragma unroll
        for (int half = 0; half < 2; half++) {
            int m = m0 + ty * 8 + 2 * i + half;
            if (m >= M) continue;
            float* src = half ? vhi : vlo;
            float* orow = out + (size_t)m * N + n0 + tx * 4;
            float r[4];
#pragma unroll
            for (int j = 0; j < 4; j++) {
                float val = src[j] + bv[j];
                if (GELU) val = val * normcdff(val);
                r[j] = val;
            }
            float4 ov;
            if (RES) {
                float4 prev = *(const float4*)orow;
                ov = make_float4(prev.x + r[0], prev.y + r[1], prev.z + r[2], prev.w + r[3]);
            } else {
                ov = make_float4(r[0], r[1], r[2], r[3]);
            }
            *(float4*)orow = ov;
        }
    }
}

// ---------------------------------------------------------------------------
// fp32 GEMM, 64x64 tile (for N=256 GEMMs) -> 2x the CTAs, near-full occupancy.
// Per kk: 2 LDS.128 + 4 pack + 8 FFMA2.
// ---------------------------------------------------------------------------
template<bool GELU, bool RES>
__global__ __launch_bounds__(256) void gemm64(const float* __restrict__ A,
                                              const float* __restrict__ W,
                                              const float* __restrict__ bias,
                                              float* __restrict__ out,
                                              int M, int K, int N) {
    __shared__ float sA[16][68];    // [k][m], 68*4=272B row (16B multiple)
    __shared__ float sB[16][64];
    int tid = threadIdx.x;
    int tx = tid & 15;              // n group
    int ty = tid >> 4;              // m group (4 rows)
    int n0 = blockIdx.x * 64;
    int m0 = blockIdx.y * 64;

    ull acc[2][4];
#pragma unroll
    for (int i = 0; i < 2; i++)
#pragma unroll
        for (int j = 0; j < 4; j++) acc[i][j] = 0ull;

    for (int k0 = 0; k0 < K; k0 += 16) {
        {
            int ml = tid >> 2;              // 0..63
            int q  = tid & 3;
            int m  = m0 + ml;
            float4 av = (m < M) ? *(const float4*)(A + (size_t)m * K + k0 + q * 4)
                                : make_float4(0.f, 0.f, 0.f, 0.f);
            sA[q * 4 + 0][ml] = av.x;
            sA[q * 4 + 1][ml] = av.y;
            sA[q * 4 + 2][ml] = av.z;
            sA[q * 4 + 3][ml] = av.w;
        }
        {
            int nl = (tid & 15) * 4;
            int kl = tid >> 4;
            *(float4*)&sB[kl][nl] = *(const float4*)(W + (size_t)(k0 + kl) * N + n0 + nl);
        }
        __syncthreads();

#pragma unroll
        for (int kk = 0; kk < 16; kk++) {
            ulonglong2 ap2 = *(const ulonglong2*)&sA[kk][ty * 4];
            float4 bf = *(const float4*)&sB[kk][tx * 4];
            ull ap[2] = {ap2.x, ap2.y};
            ull bp[4] = {pack2(bf.x, bf.x), pack2(bf.y, bf.y),
                         pack2(bf.z, bf.z), pack2(bf.w, bf.w)};
#pragma unroll
            for (int i = 0; i < 2; i++)
#pragma unroll
                for (int j = 0; j < 4; j++)
                    fma2(acc[i][j], ap[i], bp[j]);
        }
        __syncthreads();
    }

    float bv[4];
#pragma unroll
    for (int j = 0; j < 4; j++) bv[j] = bias ? bias[n0 + tx * 4 + j] : 0.f;

#pragma unroll
    for (int i = 0; i < 2; i++) {
        float vlo[4], vhi[4];
#pragma unroll
        for (int j = 0; j < 4; j++) unpack2(acc[i][j], vlo[j], vhi[j]);
#pragma unroll
        for (int half = 0; half < 2; half++) {
            int m = m0 + ty * 4 + 2 * i + half;
            if (m >= M) continue;
            float* src = half ? vhi : vlo;
            float* orow = out + (size_t)m * N + n0 + tx * 4;
            float r[4];
#pragma unroll
            for (int j = 0; j < 4; j++) {
                float val = src[j] + bv[j];
                if (GELU) val = val * normcdff(val);
                r[j] = val;
            }
            float4 ov;
            if (RES) {
                float4 prev = *(const float4*)orow;
                ov = make_float4(prev.x + r[0], prev.y + r[1], prev.z + r[2], prev.w + r[3]);
            } else {
                ov = make_float4(r[0], r[1], r[2], r[3]);
            }
            *(float4*)orow = ov;
        }
    }
}

// ---------------------------------------------------------------------------
// Split-K fused attention: grid (qt, b*h, kc). Each CTA processes KCH keys,
// emitting UNNORMALIZED partial o and partial sum l (softmax w/o max shift is
// associative across chunks). 2 queries per thread.
// ---------------------------------------------------------------------------
__global__ __launch_bounds__(128) void attn_kernel(const float* __restrict__ qkv,
                                                   float* __restrict__ opart,
                                                   float* __restrict__ lpart) {
    int bh  = blockIdx.y;
    int b   = bh >> 3;
    int h   = bh & 7;
    int kc  = blockIdx.z;
    int tid = threadIdx.x;
    int qiA = blockIdx.x * 256 + tid;
    int qiB = qiA + 128;

    __shared__ float sK[64 * 32];
    __shared__ float sV[64 * 32];

    const float scale = 0.17677669529663687f;   // 1/sqrt(32)

    ull qA[16], qB[16];
    if (qiA < N_) {
        const float4* qp = (const float4*)(qkv + (size_t)(b * N_ + qiA) * (3 * C_) + h * HD);
#pragma unroll
        for (int i = 0; i < 8; i++) {
            float4 t = qp[i];
            qA[2*i]   = pack2(t.x * scale, t.y * scale);
            qA[2*i+1] = pack2(t.z * scale, t.w * scale);
        }
    } else {
#pragma unroll
        for (int j = 0; j < 16; j++) qA[j] = 0ull;
    }
    if (qiB < N_) {
        const float4* qp = (const float4*)(qkv + (size_t)(b * N_ + qiB) * (3 * C_) + h * HD);
#pragma unroll
        for (int i = 0; i < 8; i++) {
            float4 t = qp[i];
            qB[2*i]   = pack2(t.x * scale, t.y * scale);
            qB[2*i+1] = pack2(t.z * scale, t.w * scale);
        }
    } else {
#pragma unroll
        for (int j = 0; j < 16; j++) qB[j] = 0ull;
    }

    ull oA[16], oB[16];
#pragma unroll
    for (int j = 0; j < 16; j++) { oA[j] = 0ull; oB[j] = 0ull; }
    float lA = 0.f, lB = 0.f;

    int ks = kc * KCH;
    int ke = min(N_, ks + KCH);

    for (int kb = ks; kb < ke; kb += 64) {
#pragma unroll
        for (int i = 0; i < 4; i++) {
            int idx = tid + i * 128;
            int r  = idx >> 3;
            int d4 = idx & 7;
            int m  = kb + r;
            if (m < ke) {
                size_t base = (size_t)(b * N_ + m) * (3 * C_) + h * HD + d4 * 4;
                *(float4*)&sK[r * 32 + d4 * 4] = *(const float4*)(qkv + base + C_);
                *(float4*)&sV[r * 32 + d4 * 4] = *(const float4*)(qkv + base + 2 * C_);
            }
        }
        __syncthreads();

        int rmax = min(64, ke - kb);
        for (int r = 0; r < rmax; r++) {
            const ulonglong2* kp = (const ulonglong2*)(sK + r * 32);
            ull dA0 = 0ull, dA1 = 0ull, dB0 = 0ull, dB1 = 0ull;
#pragma unroll
            for (int j = 0; j < 8; j++) {
                ulonglong2 kk2 = kp[j];
                fma2(dA0, qA[2*j],   kk2.x);
                fma2(dA1, qA[2*j+1], kk2.y);
                fma2(dB0, qB[2*j],   kk2.x);
                fma2(dB1, qB[2*j+1], kk2.y);
            }
            float pA = __expf(hsum2x2(dA0, dA1));
            float pB = __expf(hsum2x2(dB0, dB1));
            lA += pA; lB += pB;
            ull p2A = pack2(pA, pA);
            ull p2B = pack2(pB, pB);
            const ulonglong2* vp = (const ulonglong2*)(sV + r * 32);
#pragma unroll
            for (int j = 0; j < 8; j++) {
                ulonglong2 vv = vp[j];
                fma2(oA[2*j],   p2A, vv.x);
                fma2(oA[2*j+1], p2A, vv.y);
                fma2(oB[2*j],   p2B, vv.x);
                fma2(oB[2*j+1], p2B, vv.y);
            }
        }
        __syncthreads();
    }

    size_t obase = (size_t)kc * M_TOK * C_;
    size_t lbase = (size_t)kc * B_ * NH * N_ + (size_t)bh * N_;
    if (qiA < N_) {
        float* op = opart + obase + (size_t)(b * N_ + qiA) * C_ + h * HD;
#pragma unroll
        for (int j = 0; j < 16; j++) {
            float lo, hi;
            unpack2(oA[j], lo, hi);
            op[2*j] = lo; op[2*j+1] = hi;
        }
        lpart[lbase + qiA] = lA;
    }
    if (qiB < N_) {
        float* op = opart + obase + (size_t)(b * N_ + qiB) * C_ + h * HD;
#pragma unroll
        for (int j = 0; j < 16; j++) {
            float lo, hi;
            unpack2(oB[j], lo, hi);
            op[2*j] = lo; op[2*j+1] = hi;
        }
        lpart[lbase + qiB] = lB;
    }
}

// Combine split-K partials: o = (sum_kc opart) / (sum_kc lpart)
__global__ void attn_combine_kernel(const float* __restrict__ opart,
                                    const float* __restrict__ lpart,
                                    float* __restrict__ o_out) {
    int row = blockIdx.x;            // 0..M_TOK-1
    int tid = threadIdx.x;           // 0..255
    int b = row / N_, n = row % N_;
    int h = tid >> 5;

    float osum = 0.f, lsum = 0.f;
#pragma unroll
    for (int kc = 0; kc < KC; kc++) {
        osum += opart[(size_t)kc * M_TOK * C_ + (size_t)row * C_ + tid];
        lsum += lpart[(size_t)kc * B_ * NH * N_ + (size_t)(b * NH + h) * N_ + n];
    }
    o_out[(size_t)row * C_ + tid] = osum / lsum;
}

// ---------------------------------------------------------------------------
// Host launch
// ---------------------------------------------------------------------------
extern "C" void kernel_launch(void* const* d_in, const int* in_sizes, int n_in,
                              void* d_out, int out_size) {
    const float* x       = (const float*)d_in[0];
    const float* W_pe    = (const float*)d_in[1];
    const float* b_pe    = (const float*)d_in[2];
    const float* cls     = (const float*)d_in[3];
    const float* ln1_g   = (const float*)d_in[4];
    const float* ln1_b   = (const float*)d_in[5];
    const float* Wqkv    = (const float*)d_in[6];
    const float* Wproj   = (const float*)d_in[7];
    const float* bproj   = (const float*)d_in[8];
    const float* ln2_g   = (const float*)d_in[9];
    const float* ln2_b   = (const float*)d_in[10];
    const float* W1      = (const float*)d_in[11];
    const float* b1      = (const float*)d_in[12];
    const float* W2      = (const float*)d_in[13];
    const float* b2      = (const float*)d_in[14];
    const float* normf_g = (const float*)d_in[15];
    const float* normf_b = (const float*)d_in[16];
    float* out = (float*)d_out;

    float *t, *y, *qkv, *o, *h, *opart, *lpart;
    cudaGetSymbolAddress((void**)&t,     g_t);
    cudaGetSymbolAddress((void**)&y,     g_y);
    cudaGetSymbolAddress((void**)&qkv,   g_qkv);
    cudaGetSymbolAddress((void**)&o,     g_o);
    cudaGetSymbolAddress((void**)&h,     g_h);
    cudaGetSymbolAddress((void**)&opart, g_opart);
    cudaGetSymbolAddress((void**)&lpart, g_lpart);

    const int M = M_TOK;
    dim3 gridQKV(12, (M + 127) / 128);          // 128x64 tiles, N=768
    dim3 gridC(4, (M + 63) / 64);               // 64x64 tiles, N=256
    dim3 gridAttn((N_ + 255) / 256, B_ * NH, KC);

    embed_kernel<<<dim3(N_, B_), C_>>>(x, W_pe, b_pe, cls);

    for (int i = 0; i < DEPTH; i++) {
        const float* wqkv  = Wqkv  + i * C_ * 3 * C_;
        const float* wproj = Wproj + i * C_ * C_;
        const float* w1    = W1    + i * C_ * C_;
        const float* w2    = W2    + i * C_ * C_;

        ln_kernel<<<M, C_>>>(t, y, ln1_g + i * C_, ln1_b + i * C_);
        gemm128<false, false><<<gridQKV, 256>>>(y, wqkv, nullptr, qkv, M, C_, 3 * C_);
        attn_kernel<<<gridAttn, 128>>>(qkv, opart, lpart);
        attn_combine_kernel<<<M, C_>>>(opart, lpart, o);
        gemm64<false, true><<<gridC, 256>>>(o, wproj, bproj + i * C_, t, M, C_, C_);
        ln_kernel<<<M, C_>>>(t, y, ln2_g + i * C_, ln2_b + i * C_);
        gemm64<true, false><<<gridC, 256>>>(y, w1, b1 + i * C_, h, M, C_, C_);
        gemm64<false, true><<<gridC, 256>>>(h, w2, b2 + i * C_, t, M, C_, C_);
    }

    final_ln_kernel<<<M, C_>>>(t, normf_g, normf_b, out);
}

// round 8
// speedup vs baseline: 1.8022x; 1.8022x over previous
#include <cuda_runtime.h>
#include <cuda_bf16.h>

// Problem constants
#define B_   4
#define CIN  64
#define C_   256
#define N_   1729          // 1 cls + 12*12*12 tokens
#define P_   1728
#define NH   8
#define HD   32
#define DEPTH 2
#define M_TOK (B_ * N_)    // 6916
#define KC   2             // key-split chunks
#define KCH  896           // keys per chunk (14 tiles of 64)

typedef unsigned long long ull;
typedef unsigned int uint32;

// ---- packed f32x2 helpers (Blackwell FFMA2 path) ----
__device__ __forceinline__ ull pack2(float lo, float hi) {
    ull r; asm("mov.b64 %0, {%1, %2};" : "=l"(r) : "f"(lo), "f"(hi)); return r;
}
__device__ __forceinline__ void unpack2(ull v, float& lo, float& hi) {
    asm("mov.b64 {%0, %1}, %2;" : "=f"(lo), "=f"(hi) : "l"(v));
}
__device__ __forceinline__ void fma2(ull& d, ull a, ull b) {
    asm("fma.rn.f32x2 %0, %1, %2, %0;" : "+l"(d) : "l"(a), "l"(b));
}

// ---- bf16 helpers ----
__device__ __forceinline__ uint32 bf2(float lo, float hi) {
    __nv_bfloat162 t = __floats2bfloat162_rn(lo, hi);   // lo -> low 16 bits
    return *(uint32*)&t;
}

// bf16 m16n8k16 mma: D = A @ B^T + D  (A,B bf16, C/D fp32)
__device__ __forceinline__ void mma16816(float* c, const uint32* a, uint32 b0, uint32 b1) {
    asm volatile(
        "mma.sync.aligned.m16n8k16.row.col.f32.bf16.bf16.f32 "
        "{%0,%1,%2,%3}, {%4,%5,%6,%7}, {%8,%9}, {%0,%1,%2,%3};\n"
        : "+f"(c[0]), "+f"(c[1]), "+f"(c[2]), "+f"(c[3])
        : "r"(a[0]), "r"(a[1]), "r"(a[2]), "r"(a[3]), "r"(b0), "r"(b1));
}

// Scratch (device globals; no cudaMalloc allowed)
__device__ float g_t  [M_TOK * C_];
__device__ float g_y  [M_TOK * C_];
__device__ float g_qkv[M_TOK * 3 * C_];
__device__ float g_o  [M_TOK * C_];
__device__ float g_h  [M_TOK * C_];
__device__ float g_opart[KC * M_TOK * C_];          // unnormalized partial o
__device__ float g_lpart[KC * B_ * NH * N_];        // partial softmax sums

// ---------------------------------------------------------------------------
// Patch embed + cls token
// ---------------------------------------------------------------------------
__global__ void embed_kernel(const float* __restrict__ x,
                             const float* __restrict__ W_pe,
                             const float* __restrict__ b_pe,
                             const float* __restrict__ cls) {
    int n = blockIdx.x;
    int b = blockIdx.y;
    int d = threadIdx.x;
    if (n == 0) {
        g_t[(b * N_) * C_ + d] = cls[d];
        return;
    }
    int p = n - 1;
    __shared__ float sx[CIN];
    if (d < CIN) sx[d] = x[(b * CIN + d) * P_ + p];
    __syncthreads();
    float acc = b_pe[d];
#pragma unroll
    for (int c = 0; c < CIN; c++) acc += sx[c] * W_pe[c * C_ + d];
    g_t[(b * N_ + n) * C_ + d] = acc;
}

// ---------------------------------------------------------------------------
// LayerNorm (256 threads per token row)
// ---------------------------------------------------------------------------
__device__ __forceinline__ float ln_value(const float* __restrict__ in, int row, int tid,
                                          const float* __restrict__ g,
                                          const float* __restrict__ bb) {
    float v = in[row * C_ + tid];
    float s = v, sq = v * v;
#pragma unroll
    for (int o = 16; o > 0; o >>= 1) {
        s  += __shfl_down_sync(0xffffffffu, s,  o);
        sq += __shfl_down_sync(0xffffffffu, sq, o);
    }
    __shared__ float rs[8], rq[8];
    int wid = tid >> 5, lid = tid & 31;
    if (lid == 0) { rs[wid] = s; rq[wid] = sq; }
    __syncthreads();
    float sum = 0.f, sumq = 0.f;
#pragma unroll
    for (int i = 0; i < 8; i++) { sum += rs[i]; sumq += rq[i]; }
    float mean = sum * (1.f / C_);
    float var  = sumq * (1.f / C_) - mean * mean;
    float inv  = rsqrtf(var + 1e-5f);
    return (v - mean) * inv * g[tid] + bb[tid];
}

__global__ void ln_kernel(const float* __restrict__ in, float* __restrict__ out,
                          const float* __restrict__ g, const float* __restrict__ bb) {
    int row = blockIdx.x;
    int tid = threadIdx.x;
    out[row * C_ + tid] = ln_value(in, row, tid, g, bb);
}

__global__ void final_ln_kernel(const float* __restrict__ in,
                                const float* __restrict__ g, const float* __restrict__ bb,
                                float* __restrict__ out) {
    int row = blockIdx.x;
    int tid = threadIdx.x;
    float val = ln_value(in, row, tid, g, bb);
    int b = row / N_, n = row % N_;
    if (n == 0) out[b * C_ + tid] = val;
    else        out[B_ * C_ + (b * C_ + tid) * P_ + (n - 1)] = val;
}

// ---------------------------------------------------------------------------
// fp32 GEMM, 128x64 tile (for QKV, N=768).
// ---------------------------------------------------------------------------
template<bool GELU, bool RES>
__global__ __launch_bounds__(256) void gemm128(const float* __restrict__ A,
                                               const float* __restrict__ W,
                                               const float* __restrict__ bias,
                                               float* __restrict__ out,
                                               int M, int K, int N) {
    __shared__ float sA[16][132];
    __shared__ float sB[16][64];
    int tid = threadIdx.x;
    int tx = tid & 15;
    int ty = tid >> 4;
    int n0 = blockIdx.x * 64;
    int m0 = blockIdx.y * 128;

    ull acc[4][4];
#pragma unroll
    for (int i = 0; i < 4; i++)
#pragma unroll
        for (int j = 0; j < 4; j++) acc[i][j] = 0ull;

    for (int k0 = 0; k0 < K; k0 += 16) {
#pragma unroll
        for (int i = 0; i < 2; i++) {
            int idx = tid + i * 256;
            int ml  = idx >> 2;
            int q   = idx & 3;
            int m   = m0 + ml;
            float4 av = (m < M) ? *(const float4*)(A + (size_t)m * K + k0 + q * 4)
                                : make_float4(0.f, 0.f, 0.f, 0.f);
            sA[q * 4 + 0][ml] = av.x;
            sA[q * 4 + 1][ml] = av.y;
            sA[q * 4 + 2][ml] = av.z;
            sA[q * 4 + 3][ml] = av.w;
        }
        {
            int nl = (tid & 15) * 4;
            int kl = tid >> 4;
            *(float4*)&sB[kl][nl] = *(const float4*)(W + (size_t)(k0 + kl) * N + n0 + nl);
        }
        __syncthreads();

#pragma unroll
        for (int kk = 0; kk < 16; kk++) {
            ulonglong2 a01 = *(const ulonglong2*)&sA[kk][ty * 8];
            ulonglong2 a23 = *(const ulonglong2*)&sA[kk][ty * 8 + 4];
            float4 bf = *(const float4*)&sB[kk][tx * 4];
            ull ap[4] = {a01.x, a01.y, a23.x, a23.y};
            ull bp[4] = {pack2(bf.x, bf.x), pack2(bf.y, bf.y),
                         pack2(bf.z, bf.z), pack2(bf.w, bf.w)};
#pragma unroll
            for (int i = 0; i < 4; i++)
#pragma unroll
                for (int j = 0; j < 4; j++)
                    fma2(acc[i][j], ap[i], bp[j]);
        }
        __syncthreads();
    }

    float bv[4];
#pragma unroll
    for (int j = 0; j < 4; j++) bv[j] = bias ? bias[n0 + tx * 4 + j] : 0.f;

#pragma unroll
    for (int i = 0; i < 4; i++) {
        float vlo[4], vhi[4];
#pragma unroll
        for (int j = 0; j < 4; j++) unpack2(acc[i][j], vlo[j], vhi[j]);
#pragma unroll
        for (int half = 0; half < 2; half++) {
            int m = m0 + ty * 8 + 2 * i + half;
            if (m >= M) continue;
            float* src = half ? vhi : vlo;
            float* orow = out + (size_t)m * N + n0 + tx * 4;
            float r[4];
#pragma unroll
            for (int j = 0; j < 4; j++) {
                float val = src[j] + bv[j];
                if (GELU) val = val * normcdff(val);
                r[j] = val;
            }
            float4 ov;
            if (RES) {
                float4 prev = *(const float4*)orow;
                ov = make_float4(prev.x + r[0], prev.y + r[1], prev.z + r[2], prev.w + r[3]);
            } else {
                ov = make_float4(r[0], r[1], r[2], r[3]);
            }
            *(float4*)orow = ov;
        }
    }
}

// ---------------------------------------------------------------------------
// fp32 GEMM, 64x64 tile (for N=256 GEMMs).
// ---------------------------------------------------------------------------
template<bool GELU, bool RES>
__global__ __launch_bounds__(256) void gemm64(const float* __restrict__ A,
                                              const float* __restrict__ W,
                                              const float* __restrict__ bias,
                                              float* __restrict__ out,
                                              int M, int K, int N) {
    __shared__ float sA[16][68];
    __shared__ float sB[16][64];
    int tid = threadIdx.x;
    int tx = tid & 15;
    int ty = tid >> 4;
    int n0 = blockIdx.x * 64;
    int m0 = blockIdx.y * 64;

    ull acc[2][4];
#pragma unroll
    for (int i = 0; i < 2; i++)
#pragma unroll
        for (int j = 0; j < 4; j++) acc[i][j] = 0ull;

    for (int k0 = 0; k0 < K; k0 += 16) {
        {
            int ml = tid >> 2;
            int q  = tid & 3;
            int m  = m0 + ml;
            float4 av = (m < M) ? *(const float4*)(A + (size_t)m * K + k0 + q * 4)
                                : make_float4(0.f, 0.f, 0.f, 0.f);
            sA[q * 4 + 0][ml] = av.x;
            sA[q * 4 + 1][ml] = av.y;
            sA[q * 4 + 2][ml] = av.z;
            sA[q * 4 + 3][ml] = av.w;
        }
        {
            int nl = (tid & 15) * 4;
            int kl = tid >> 4;
            *(float4*)&sB[kl][nl] = *(const float4*)(W + (size_t)(k0 + kl) * N + n0 + nl);
        }
        __syncthreads();

#pragma unroll
        for (int kk = 0; kk < 16; kk++) {
            ulonglong2 ap2 = *(const ulonglong2*)&sA[kk][ty * 4];
            float4 bf = *(const float4*)&sB[kk][tx * 4];
            ull ap[2] = {ap2.x, ap2.y};
            ull bp[4] = {pack2(bf.x, bf.x), pack2(bf.y, bf.y),
                         pack2(bf.z, bf.z), pack2(bf.w, bf.w)};
#pragma unroll
            for (int i = 0; i < 2; i++)
#pragma unroll
                for (int j = 0; j < 4; j++)
                    fma2(acc[i][j], ap[i], bp[j]);
        }
        __syncthreads();
    }

    float bv[4];
#pragma unroll
    for (int j = 0; j < 4; j++) bv[j] = bias ? bias[n0 + tx * 4 + j] : 0.f;

#pragma unroll
    for (int i = 0; i < 2; i++) {
        float vlo[4], vhi[4];
#pragma unroll
        for (int j = 0; j < 4; j++) unpack2(acc[i][j], vlo[j], vhi[j]);
#pragma unroll
        for (int half = 0; half < 2; half++) {
            int m = m0 + ty * 4 + 2 * i + half;
            if (m >= M) continue;
            float* src = half ? vhi : vlo;
            float* orow = out + (size_t)m * N + n0 + tx * 4;
            float r[4];
#pragma unroll
            for (int j = 0; j < 4; j++) {
                float val = src[j] + bv[j];
                if (GELU) val = val * normcdff(val);
                r[j] = val;
            }
            float4 ov;
            if (RES) {
                float4 prev = *(const float4*)orow;
                ov = make_float4(prev.x + r[0], prev.y + r[1], prev.z + r[2], prev.w + r[3]);
            } else {
                ov = make_float4(r[0], r[1], r[2], r[3]);
            }
            *(float4*)orow = ov;
        }
    }
}

// ---------------------------------------------------------------------------
// bf16 tensor-core flash attention (split-K, no max-subtraction softmax).
// Grid: (qtile 0..27, b*h, kc). CTA = 128 threads = 4 warps; warp owns 16 queries
// (m16), 64 queries/CTA. Key tiles of 64. S = Q@K^T via m16n8k16 (K tile fed
// directly as B, row.col = A@B^T). exp in fp32 regs, repacked to bf16x2 which
// IS the A-fragment layout for P@V (C-layout == A-layout for k16 mma).
// V transposed into smem for the P@V B operand. Emits unnormalized partials.
// ---------------------------------------------------------------------------
__global__ __launch_bounds__(128) void attn_kernel(const float* __restrict__ qkv,
                                                   float* __restrict__ opart,
                                                   float* __restrict__ lpart) {
    int qt  = blockIdx.x;
    int bh  = blockIdx.y;
    int b   = bh >> 3;
    int h   = bh & 7;
    int kc  = blockIdx.z;
    int tid = threadIdx.x;
    int warp = tid >> 5, lane = tid & 31;
    int g = lane >> 2, qd = lane & 3;

    __shared__ __nv_bfloat16 sK [64][34];   // [key][dim], padded
    __shared__ __nv_bfloat16 sVt[32][68];   // [dim][key], padded

    const float scale = 0.17677669529663687f;   // 1/sqrt(32)

    // Warp's query rows
    int rowA = qt * 64 + warp * 16 + g;      // row g
    int rowB = rowA + 8;                     // row g+8
    int rAc = min(rowA, N_ - 1);
    int rBc = min(rowB, N_ - 1);

    // Q fragments: 2 k-steps (k16) x 4 bf16x2 regs, pre-scaled
    uint32 qa[2][4];
    {
        const float* qA = qkv + (size_t)(b * N_ + rAc) * (3 * C_) + h * HD;
        const float* qB = qkv + (size_t)(b * N_ + rBc) * (3 * C_) + h * HD;
#pragma unroll
        for (int kk = 0; kk < 2; kk++) {
            int c0 = kk * 16 + 2 * qd;
            float2 a0 = *(const float2*)(qA + c0);
            float2 a1 = *(const float2*)(qB + c0);
            float2 a2 = *(const float2*)(qA + c0 + 8);
            float2 a3 = *(const float2*)(qB + c0 + 8);
            qa[kk][0] = bf2(a0.x * scale, a0.y * scale);
            qa[kk][1] = bf2(a1.x * scale, a1.y * scale);
            qa[kk][2] = bf2(a2.x * scale, a2.y * scale);
            qa[kk][3] = bf2(a3.x * scale, a3.y * scale);
        }
    }

    float oacc[4][4];
#pragma unroll
    for (int i = 0; i < 4; i++)
#pragma unroll
        for (int j = 0; j < 4; j++) oacc[i][j] = 0.f;
    float lA = 0.f, lB = 0.f;

    int ks = kc * KCH;
    int ke = min(N_, ks + KCH);

    for (int kb = ks; kb < ke; kb += 64) {
        // Load K/V tile (fp32 gmem -> bf16 smem; V transposed)
#pragma unroll
        for (int i = 0; i < 4; i++) {
            int idx = tid + i * 128;        // 0..511
            int key = idx >> 3;             // 0..63
            int d4  = idx & 7;              // float4 within 32 dims
            int m   = kb + key;
            int mc  = min(m, N_ - 1);
            size_t base = (size_t)(b * N_ + mc) * (3 * C_) + h * HD + d4 * 4;
            float4 kv = *(const float4*)(qkv + base + C_);
            float4 vv = *(const float4*)(qkv + base + 2 * C_);
            *(__nv_bfloat162*)&sK[key][d4 * 4]     = __floats2bfloat162_rn(kv.x, kv.y);
            *(__nv_bfloat162*)&sK[key][d4 * 4 + 2] = __floats2bfloat162_rn(kv.z, kv.w);
            sVt[d4 * 4 + 0][key] = __float2bfloat16(vv.x);
            sVt[d4 * 4 + 1][key] = __float2bfloat16(vv.y);
            sVt[d4 * 4 + 2][key] = __float2bfloat16(vv.z);
            sVt[d4 * 4 + 3][key] = __float2bfloat16(vv.w);
        }
        __syncthreads();

        // S = Q @ K^T  (8 n-steps over 64 keys, 2 k-steps over 32 dims)
        float sacc[8][4];
#pragma unroll
        for (int ns = 0; ns < 8; ns++)
#pragma unroll
            for (int j = 0; j < 4; j++) sacc[ns][j] = 0.f;
#pragma unroll
        for (int ns = 0; ns < 8; ns++) {
#pragma unroll
            for (int kk = 0; kk < 2; kk++) {
                uint32 b0 = *(const uint32*)&sK[ns * 8 + g][kk * 16 + 2 * qd];
                uint32 b1 = *(const uint32*)&sK[ns * 8 + g][kk * 16 + 2 * qd + 8];
                mma16816(sacc[ns], qa[kk], b0, b1);
            }
        }

        // softmax (no max shift) + pack P as bf16 A-fragments
        uint32 pa[4][4];
#pragma unroll
        for (int ns = 0; ns < 8; ns++) {
            int cb = kb + ns * 8 + 2 * qd;
            float p0 = (cb     < N_) ? __expf(sacc[ns][0]) : 0.f;
            float p1 = (cb + 1 < N_) ? __expf(sacc[ns][1]) : 0.f;
            float p2 = (cb     < N_) ? __expf(sacc[ns][2]) : 0.f;
            float p3 = (cb + 1 < N_) ? __expf(sacc[ns][3]) : 0.f;
            lA += p0 + p1;
            lB += p2 + p3;
            int kk = ns >> 1;
            if (ns & 1) { pa[kk][2] = bf2(p0, p1); pa[kk][3] = bf2(p2, p3); }
            else        { pa[kk][0] = bf2(p0, p1); pa[kk][1] = bf2(p2, p3); }
        }

        // O += P @ V  (4 n-steps over 32 dims, 4 k-steps over 64 keys)
#pragma unroll
        for (int nd = 0; nd < 4; nd++) {
#pragma unroll
            for (int kk = 0; kk < 4; kk++) {
                uint32 b0 = *(const uint32*)&sVt[nd * 8 + g][kk * 16 + 2 * qd];
                uint32 b1 = *(const uint32*)&sVt[nd * 8 + g][kk * 16 + 2 * qd + 8];
                mma16816(oacc[nd], pa[kk], b0, b1);
            }
        }
        __syncthreads();
    }

    // quad-reduce l (cols are spread over the 4 lanes of each quad)
    lA += __shfl_xor_sync(0xffffffffu, lA, 1);
    lA += __shfl_xor_sync(0xffffffffu, lA, 2);
    lB += __shfl_xor_sync(0xffffffffu, lB, 1);
    lB += __shfl_xor_sync(0xffffffffu, lB, 2);

    size_t obase = (size_t)kc * M_TOK * C_;
    size_t lbase = (size_t)kc * B_ * NH * N_ + (size_t)bh * N_;
    if (rowA < N_) {
        float* op = opart + obase + (size_t)(b * N_ + rowA) * C_ + h * HD;
#pragma unroll
        for (int nd = 0; nd < 4; nd++)
            *(float2*)(op + nd * 8 + 2 * qd) = make_float2(oacc[nd][0], oacc[nd][1]);
        if (qd == 0) lpart[lbase + rowA] = lA;
    }
    if (rowB < N_) {
        float* op = opart + obase + (size_t)(b * N_ + rowB) * C_ + h * HD;
#pragma unroll
        for (int nd = 0; nd < 4; nd++)
            *(float2*)(op + nd * 8 + 2 * qd) = make_float2(oacc[nd][2], oacc[nd][3]);
        if (qd == 0) lpart[lbase + rowB] = lB;
    }
}

// Combine split-K partials: o = (sum_kc opart) / (sum_kc lpart)
__global__ void attn_combine_kernel(const float* __restrict__ opart,
                                    const float* __restrict__ lpart,
                                    float* __restrict__ o_out) {
    int row = blockIdx.x;
    int tid = threadIdx.x;
    int b = row / N_, n = row % N_;
    int h = tid >> 5;

    float osum = 0.f, lsum = 0.f;
#pragma unroll
    for (int kc = 0; kc < KC; kc++) {
        osum += opart[(size_t)kc * M_TOK * C_ + (size_t)row * C_ + tid];
        lsum += lpart[(size_t)kc * B_ * NH * N_ + (size_t)(b * NH + h) * N_ + n];
    }
    o_out[(size_t)row * C_ + tid] = osum / lsum;
}

// ---------------------------------------------------------------------------
// Host launch
// ---------------------------------------------------------------------------
extern "C" void kernel_launch(void* const* d_in, const int* in_sizes, int n_in,
                              void* d_out, int out_size) {
    const float* x       = (const float*)d_in[0];
    const float* W_pe    = (const float*)d_in[1];
    const float* b_pe    = (const float*)d_in[2];
    const float* cls     = (const float*)d_in[3];
    const float* ln1_g   = (const float*)d_in[4];
    const float* ln1_b   = (const float*)d_in[5];
    const float* Wqkv    = (const float*)d_in[6];
    const float* Wproj   = (const float*)d_in[7];
    const float* bproj   = (const float*)d_in[8];
    const float* ln2_g   = (const float*)d_in[9];
    const float* ln2_b   = (const float*)d_in[10];
    const float* W1      = (const float*)d_in[11];
    const float* b1      = (const float*)d_in[12];
    const float* W2      = (const float*)d_in[13];
    const float* b2      = (const float*)d_in[14];
    const float* normf_g = (const float*)d_in[15];
    const float* normf_b = (const float*)d_in[16];
    float* out = (float*)d_out;

    float *t, *y, *qkv, *o, *h, *opart, *lpart;
    cudaGetSymbolAddress((void**)&t,     g_t);
    cudaGetSymbolAddress((void**)&y,     g_y);
    cudaGetSymbolAddress((void**)&qkv,   g_qkv);
    cudaGetSymbolAddress((void**)&o,     g_o);
    cudaGetSymbolAddress((void**)&h,     g_h);
    cudaGetSymbolAddress((void**)&opart, g_opart);
    cudaGetSymbolAddress((void**)&lpart, g_lpart);

    const int M = M_TOK;
    dim3 gridQKV(12, (M + 127) / 128);          // 128x64 tiles, N=768
    dim3 gridC(4, (M + 63) / 64);               // 64x64 tiles, N=256
    dim3 gridAttn((N_ + 63) / 64, B_ * NH, KC);

    embed_kernel<<<dim3(N_, B_), C_>>>(x, W_pe, b_pe, cls);

    for (int i = 0; i < DEPTH; i++) {
        const float* wqkv  = Wqkv  + i * C_ * 3 * C_;
        const float* wproj = Wproj + i * C_ * C_;
        const float* w1    = W1    + i * C_ * C_;
        const float* w2    = W2    + i * C_ * C_;

        ln_kernel<<<M, C_>>>(t, y, ln1_g + i * C_, ln1_b + i * C_);
        gemm128<false, false><<<gridQKV, 256>>>(y, wqkv, nullptr, qkv, M, C_, 3 * C_);
        attn_kernel<<<gridAttn, 128>>>(qkv, opart, lpart);
        attn_combine_kernel<<<M, C_>>>(opart, lpart, o);
        gemm64<false, true><<<gridC, 256>>>(o, wproj, bproj + i * C_, t, M, C_, C_);
        ln_kernel<<<M, C_>>>(t, y, ln2_g + i * C_, ln2_b + i * C_);
        gemm64<true, false><<<gridC, 256>>>(y, w1, b1 + i * C_, h, M, C_, C_);
        gemm64<false, true><<<gridC, 256>>>(h, w2, b2 + i * C_, t, M, C_, C_);
    }

    final_ln_kernel<<<M, C_>>>(t, normf_g, normf_b, out);
}

// round 9
// speedup vs baseline: 2.2749x; 1.2623x over previous
#include <cuda_runtime.h>
#include <cuda_bf16.h>

// Problem constants
#define B_   4
#define CIN  64
#define C_   256
#define N_   1729          // 1 cls + 12*12*12 tokens
#define P_   1728
#define NH   8
#define HD   32
#define DEPTH 2
#define M_TOK (B_ * N_)    // 6916
#define KC   2             // key-split chunks
#define KCH  896           // keys per chunk (14 tiles of 64)

typedef unsigned long long ull;
typedef unsigned int uint32;

// ---- bf16 helpers ----
__device__ __forceinline__ uint32 bf2(float lo, float hi) {
    __nv_bfloat162 t = __floats2bfloat162_rn(lo, hi);   // lo -> low 16 bits
    return *(uint32*)&t;
}

// bf16 m16n8k16 mma: D = A @ B^T + D  (A,B bf16, C/D fp32)
__device__ __forceinline__ void mma16816(float* c, const uint32* a, uint32 b0, uint32 b1) {
    asm volatile(
        "mma.sync.aligned.m16n8k16.row.col.f32.bf16.bf16.f32 "
        "{%0,%1,%2,%3}, {%4,%5,%6,%7}, {%8,%9}, {%0,%1,%2,%3};\n"
        : "+f"(c[0]), "+f"(c[1]), "+f"(c[2]), "+f"(c[3])
        : "r"(a[0]), "r"(a[1]), "r"(a[2]), "r"(a[3]), "r"(b0), "r"(b1));
}

// tf32 m16n8k8 mma
__device__ __forceinline__ void mma_tf32(float* c, const uint32* a, uint32 b0, uint32 b1) {
    asm volatile(
        "mma.sync.aligned.m16n8k8.row.col.f32.tf32.tf32.f32 "
        "{%0,%1,%2,%3}, {%4,%5,%6,%7}, {%8,%9}, {%0,%1,%2,%3};\n"
        : "+f"(c[0]), "+f"(c[1]), "+f"(c[2]), "+f"(c[3])
        : "r"(a[0]), "r"(a[1]), "r"(a[2]), "r"(a[3]), "r"(b0), "r"(b1));
}

__device__ __forceinline__ float cvt_tf32f(float f) {
    uint32 r; asm("cvt.rna.tf32.f32 %0, %1;" : "=r"(r) : "f"(f));
    return __uint_as_float(r);
}

// Scratch (device globals; no cudaMalloc allowed)
__device__ float g_t  [M_TOK * C_];
__device__ float g_y  [M_TOK * C_];
__device__ float g_qkv[M_TOK * 3 * C_];
__device__ float g_o  [M_TOK * C_];
__device__ float g_h  [M_TOK * C_];
__device__ float g_opart[KC * M_TOK * C_];          // unnormalized partial o
__device__ float g_lpart[KC * B_ * NH * N_];        // partial softmax sums

// ---------------------------------------------------------------------------
// Patch embed + cls token
// ---------------------------------------------------------------------------
__global__ void embed_kernel(const float* __restrict__ x,
                             const float* __restrict__ W_pe,
                             const float* __restrict__ b_pe,
                             const float* __restrict__ cls) {
    int n = blockIdx.x;
    int b = blockIdx.y;
    int d = threadIdx.x;
    if (n == 0) {
        g_t[(b * N_) * C_ + d] = cls[d];
        return;
    }
    int p = n - 1;
    __shared__ float sx[CIN];
    if (d < CIN) sx[d] = x[(b * CIN + d) * P_ + p];
    __syncthreads();
    float acc = b_pe[d];
#pragma unroll
    for (int c = 0; c < CIN; c++) acc += sx[c] * W_pe[c * C_ + d];
    g_t[(b * N_ + n) * C_ + d] = acc;
}

// ---------------------------------------------------------------------------
// LayerNorm (256 threads per token row)
// ---------------------------------------------------------------------------
__device__ __forceinline__ float ln_value(const float* __restrict__ in, int row, int tid,
                                          const float* __restrict__ g,
                                          const float* __restrict__ bb) {
    float v = in[row * C_ + tid];
    float s = v, sq = v * v;
#pragma unroll
    for (int o = 16; o > 0; o >>= 1) {
        s  += __shfl_down_sync(0xffffffffu, s,  o);
        sq += __shfl_down_sync(0xffffffffu, sq, o);
    }
    __shared__ float rs[8], rq[8];
    int wid = tid >> 5, lid = tid & 31;
    if (lid == 0) { rs[wid] = s; rq[wid] = sq; }
    __syncthreads();
    float sum = 0.f, sumq = 0.f;
#pragma unroll
    for (int i = 0; i < 8; i++) { sum += rs[i]; sumq += rq[i]; }
    float mean = sum * (1.f / C_);
    float var  = sumq * (1.f / C_) - mean * mean;
    float inv  = rsqrtf(var + 1e-5f);
    return (v - mean) * inv * g[tid] + bb[tid];
}

__global__ void ln_kernel(const float* __restrict__ in, float* __restrict__ out,
                          const float* __restrict__ g, const float* __restrict__ bb) {
    int row = blockIdx.x;
    int tid = threadIdx.x;
    out[row * C_ + tid] = ln_value(in, row, tid, g, bb);
}

__global__ void final_ln_kernel(const float* __restrict__ in,
                                const float* __restrict__ g, const float* __restrict__ bb,
                                float* __restrict__ out) {
    int row = blockIdx.x;
    int tid = threadIdx.x;
    float val = ln_value(in, row, tid, g, bb);
    int b = row / N_, n = row % N_;
    if (n == 0) out[b * C_ + tid] = val;
    else        out[B_ * C_ + (b * C_ + tid) * P_ + (n - 1)] = val;
}

// ---------------------------------------------------------------------------
// tf32 tensor-core GEMM: out[M,N] = act(A[M,K] @ W[K,N] + bias) (+= if RES).
// BM=BN=64, BK=16, 128 threads = 4 warps (2m x 2n), warp = 32x32 via
// 2(m16) x 4(n8) mma.m16n8k8 tiles. Inputs tf32-rounded once at smem fill.
// N % 64 == 0 and K % 16 == 0 always; only M is guarded.
// ---------------------------------------------------------------------------
template<bool GELU, bool RES>
__global__ __launch_bounds__(128) void gemm_tf32(const float* __restrict__ A,
                                                 const float* __restrict__ W,
                                                 const float* __restrict__ bias,
                                                 float* __restrict__ out,
                                                 int M, int K, int N) {
    __shared__ float sA[64][20];    // [m][k], stride 20 -> conflict-free frag reads
    __shared__ float sB[16][68];    // [k][n]
    int tid  = threadIdx.x;
    int warp = tid >> 5, lane = tid & 31;
    int g = lane >> 2, qd = lane & 3;
    int wm = warp >> 1, wn = warp & 1;
    int m0 = blockIdx.y * 64;
    int n0 = blockIdx.x * 64;

    float c[2][4][4];
#pragma unroll
    for (int mt = 0; mt < 2; mt++)
#pragma unroll
        for (int nt = 0; nt < 4; nt++)
#pragma unroll
            for (int j = 0; j < 4; j++) c[mt][nt][j] = 0.f;

    for (int k0 = 0; k0 < K; k0 += 16) {
        // A tile: 64 x 16 = 256 float4, 2 per thread
#pragma unroll
        for (int i = 0; i < 2; i++) {
            int idx = tid + i * 128;
            int m = idx >> 2, q = idx & 3;
            int gm = m0 + m;
            float4 av = (gm < M) ? *(const float4*)(A + (size_t)gm * K + k0 + q * 4)
                                 : make_float4(0.f, 0.f, 0.f, 0.f);
            av.x = cvt_tf32f(av.x); av.y = cvt_tf32f(av.y);
            av.z = cvt_tf32f(av.z); av.w = cvt_tf32f(av.w);
            *(float4*)&sA[m][q * 4] = av;
        }
        // B tile: 16 x 64 = 256 float4, 2 per thread
#pragma unroll
        for (int i = 0; i < 2; i++) {
            int idx = tid + i * 128;
            int kl = idx >> 4, nl = (idx & 15) * 4;
            float4 bv4 = *(const float4*)(W + (size_t)(k0 + kl) * N + n0 + nl);
            bv4.x = cvt_tf32f(bv4.x); bv4.y = cvt_tf32f(bv4.y);
            bv4.z = cvt_tf32f(bv4.z); bv4.w = cvt_tf32f(bv4.w);
            *(float4*)&sB[kl][nl] = bv4;
        }
        __syncthreads();

#pragma unroll
        for (int ks = 0; ks < 2; ks++) {
            int k8 = ks * 8;
            uint32 a[2][4];
#pragma unroll
            for (int mt = 0; mt < 2; mt++) {
                int mrow = wm * 32 + mt * 16 + g;
                a[mt][0] = __float_as_uint(sA[mrow    ][qd + k8]);
                a[mt][1] = __float_as_uint(sA[mrow + 8][qd + k8]);
                a[mt][2] = __float_as_uint(sA[mrow    ][qd + 4 + k8]);
                a[mt][3] = __float_as_uint(sA[mrow + 8][qd + 4 + k8]);
            }
#pragma unroll
            for (int nt = 0; nt < 4; nt++) {
                int ncol = wn * 32 + nt * 8 + g;
                uint32 b0 = __float_as_uint(sB[qd + k8    ][ncol]);
                uint32 b1 = __float_as_uint(sB[qd + 4 + k8][ncol]);
#pragma unroll
                for (int mt = 0; mt < 2; mt++)
                    mma_tf32(c[mt][nt], a[mt], b0, b1);
            }
        }
        __syncthreads();
    }

    // Epilogue: c[mt][nt] -> rows (m0+wm*32+mt*16+g, +8), cols (n0+wn*32+nt*8+2qd, +1)
#pragma unroll
    for (int nt = 0; nt < 4; nt++) {
        int col = n0 + wn * 32 + nt * 8 + 2 * qd;
        float bv0 = bias ? bias[col]     : 0.f;
        float bv1 = bias ? bias[col + 1] : 0.f;
#pragma unroll
        for (int mt = 0; mt < 2; mt++) {
            int row0 = m0 + wm * 32 + mt * 16 + g;
#pragma unroll
            for (int half = 0; half < 2; half++) {
                int row = row0 + half * 8;
                if (row >= M) continue;
                float v0 = c[mt][nt][half * 2]     + bv0;
                float v1 = c[mt][nt][half * 2 + 1] + bv1;
                if (GELU) { v0 = v0 * normcdff(v0); v1 = v1 * normcdff(v1); }
                float* op = out + (size_t)row * N + col;
                if (RES) {
                    float2 prev = *(const float2*)op;
                    *(float2*)op = make_float2(prev.x + v0, prev.y + v1);
                } else {
                    *(float2*)op = make_float2(v0, v1);
                }
            }
        }
    }
}

// ---------------------------------------------------------------------------
// bf16 tensor-core flash attention (split-K, no max-subtraction softmax).
// ---------------------------------------------------------------------------
__global__ __launch_bounds__(128) void attn_kernel(const float* __restrict__ qkv,
                                                   float* __restrict__ opart,
                                                   float* __restrict__ lpart) {
    int qt  = blockIdx.x;
    int bh  = blockIdx.y;
    int b   = bh >> 3;
    int h   = bh & 7;
    int kc  = blockIdx.z;
    int tid = threadIdx.x;
    int warp = tid >> 5, lane = tid & 31;
    int g = lane >> 2, qd = lane & 3;

    __shared__ __nv_bfloat16 sK [64][34];   // [key][dim], padded
    __shared__ __nv_bfloat16 sVt[32][68];   // [dim][key], padded

    const float scale = 0.17677669529663687f;   // 1/sqrt(32)

    int rowA = qt * 64 + warp * 16 + g;
    int rowB = rowA + 8;
    int rAc = min(rowA, N_ - 1);
    int rBc = min(rowB, N_ - 1);

    uint32 qa[2][4];
    {
        const float* qA = qkv + (size_t)(b * N_ + rAc) * (3 * C_) + h * HD;
        const float* qB = qkv + (size_t)(b * N_ + rBc) * (3 * C_) + h * HD;
#pragma unroll
        for (int kk = 0; kk < 2; kk++) {
            int c0 = kk * 16 + 2 * qd;
            float2 a0 = *(const float2*)(qA + c0);
            float2 a1 = *(const float2*)(qB + c0);
            float2 a2 = *(const float2*)(qA + c0 + 8);
            float2 a3 = *(const float2*)(qB + c0 + 8);
            qa[kk][0] = bf2(a0.x * scale, a0.y * scale);
            qa[kk][1] = bf2(a1.x * scale, a1.y * scale);
            qa[kk][2] = bf2(a2.x * scale, a2.y * scale);
            qa[kk][3] = bf2(a3.x * scale, a3.y * scale);
        }
    }

    float oacc[4][4];
#pragma unroll
    for (int i = 0; i < 4; i++)
#pragma unroll
        for (int j = 0; j < 4; j++) oacc[i][j] = 0.f;
    float lA = 0.f, lB = 0.f;

    int ks = kc * KCH;
    int ke = min(N_, ks + KCH);

    for (int kb = ks; kb < ke; kb += 64) {
#pragma unroll
        for (int i = 0; i < 4; i++) {
            int idx = tid + i * 128;
            int key = idx >> 3;
            int d4  = idx & 7;
            int m   = kb + key;
            int mc  = min(m, N_ - 1);
            size_t base = (size_t)(b * N_ + mc) * (3 * C_) + h * HD + d4 * 4;
            float4 kv = *(const float4*)(qkv + base + C_);
            float4 vv = *(const float4*)(qkv + base + 2 * C_);
            *(__nv_bfloat162*)&sK[key][d4 * 4]     = __floats2bfloat162_rn(kv.x, kv.y);
            *(__nv_bfloat162*)&sK[key][d4 * 4 + 2] = __floats2bfloat162_rn(kv.z, kv.w);
            sVt[d4 * 4 + 0][key] = __float2bfloat16(vv.x);
            sVt[d4 * 4 + 1][key] = __float2bfloat16(vv.y);
            sVt[d4 * 4 + 2][key] = __float2bfloat16(vv.z);
            sVt[d4 * 4 + 3][key] = __float2bfloat16(vv.w);
        }
        __syncthreads();

        float sacc[8][4];
#pragma unroll
        for (int ns = 0; ns < 8; ns++)
#pragma unroll
            for (int j = 0; j < 4; j++) sacc[ns][j] = 0.f;
#pragma unroll
        for (int ns = 0; ns < 8; ns++) {
#pragma unroll
            for (int kk = 0; kk < 2; kk++) {
                uint32 b0 = *(const uint32*)&sK[ns * 8 + g][kk * 16 + 2 * qd];
                uint32 b1 = *(const uint32*)&sK[ns * 8 + g][kk * 16 + 2 * qd + 8];
                mma16816(sacc[ns], qa[kk], b0, b1);
            }
        }

        uint32 pa[4][4];
#pragma unroll
        for (int ns = 0; ns < 8; ns++) {
            int cb = kb + ns * 8 + 2 * qd;
            float p0 = (cb     < N_) ? __expf(sacc[ns][0]) : 0.f;
            float p1 = (cb + 1 < N_) ? __expf(sacc[ns][1]) : 0.f;
            float p2 = (cb     < N_) ? __expf(sacc[ns][2]) : 0.f;
            float p3 = (cb + 1 < N_) ? __expf(sacc[ns][3]) : 0.f;
            lA += p0 + p1;
            lB += p2 + p3;
            int kk = ns >> 1;
            if (ns & 1) { pa[kk][2] = bf2(p0, p1); pa[kk][3] = bf2(p2, p3); }
            else        { pa[kk][0] = bf2(p0, p1); pa[kk][1] = bf2(p2, p3); }
        }

#pragma unroll
        for (int nd = 0; nd < 4; nd++) {
#pragma unroll
            for (int kk = 0; kk < 4; kk++) {
                uint32 b0 = *(const uint32*)&sVt[nd * 8 + g][kk * 16 + 2 * qd];
                uint32 b1 = *(const uint32*)&sVt[nd * 8 + g][kk * 16 + 2 * qd + 8];
                mma16816(oacc[nd], pa[kk], b0, b1);
            }
        }
        __syncthreads();
    }

    lA += __shfl_xor_sync(0xffffffffu, lA, 1);
    lA += __shfl_xor_sync(0xffffffffu, lA, 2);
    lB += __shfl_xor_sync(0xffffffffu, lB, 1);
    lB += __shfl_xor_sync(0xffffffffu, lB, 2);

    size_t obase = (size_t)kc * M_TOK * C_;
    size_t lbase = (size_t)kc * B_ * NH * N_ + (size_t)bh * N_;
    if (rowA < N_) {
        float* op = opart + obase + (size_t)(b * N_ + rowA) * C_ + h * HD;
#pragma unroll
        for (int nd = 0; nd < 4; nd++)
            *(float2*)(op + nd * 8 + 2 * qd) = make_float2(oacc[nd][0], oacc[nd][1]);
        if (qd == 0) lpart[lbase + rowA] = lA;
    }
    if (rowB < N_) {
        float* op = opart + obase + (size_t)(b * N_ + rowB) * C_ + h * HD;
#pragma unroll
        for (int nd = 0; nd < 4; nd++)
            *(float2*)(op + nd * 8 + 2 * qd) = make_float2(oacc[nd][2], oacc[nd][3]);
        if (qd == 0) lpart[lbase + rowB] = lB;
    }
}

// Combine split-K partials: o = (sum_kc opart) / (sum_kc lpart)
__global__ void attn_combine_kernel(const float* __restrict__ opart,
                                    const float* __restrict__ lpart,
                                    float* __restrict__ o_out) {
    int row = blockIdx.x;
    int tid = threadIdx.x;
    int b = row / N_, n = row % N_;
    int h = tid >> 5;

    float osum = 0.f, lsum = 0.f;
#pragma unroll
    for (int kc = 0; kc < KC; kc++) {
        osum += opart[(size_t)kc * M_TOK * C_ + (size_t)row * C_ + tid];
        lsum += lpart[(size_t)kc * B_ * NH * N_ + (size_t)(b * NH + h) * N_ + n];
    }
    o_out[(size_t)row * C_ + tid] = osum / lsum;
}

// ---------------------------------------------------------------------------
// Host launch
// ---------------------------------------------------------------------------
extern "C" void kernel_launch(void* const* d_in, const int* in_sizes, int n_in,
                              void* d_out, int out_size) {
    const float* x       = (const float*)d_in[0];
    const float* W_pe    = (const float*)d_in[1];
    const float* b_pe    = (const float*)d_in[2];
    const float* cls     = (const float*)d_in[3];
    const float* ln1_g   = (const float*)d_in[4];
    const float* ln1_b   = (const float*)d_in[5];
    const float* Wqkv    = (const float*)d_in[6];
    const float* Wproj   = (const float*)d_in[7];
    const float* bproj   = (const float*)d_in[8];
    const float* ln2_g   = (const float*)d_in[9];
    const float* ln2_b   = (const float*)d_in[10];
    const float* W1      = (const float*)d_in[11];
    const float* b1      = (const float*)d_in[12];
    const float* W2      = (const float*)d_in[13];
    const float* b2      = (const float*)d_in[14];
    const float* normf_g = (const float*)d_in[15];
    const float* normf_b = (const float*)d_in[16];
    float* out = (float*)d_out;

    float *t, *y, *qkv, *o, *h, *opart, *lpart;
    cudaGetSymbolAddress((void**)&t,     g_t);
    cudaGetSymbolAddress((void**)&y,     g_y);
    cudaGetSymbolAddress((void**)&qkv,   g_qkv);
    cudaGetSymbolAddress((void**)&o,     g_o);
    cudaGetSymbolAddress((void**)&h,     g_h);
    cudaGetSymbolAddress((void**)&opart, g_opart);
    cudaGetSymbolAddress((void**)&lpart, g_lpart);

    const int M = M_TOK;
    int mtiles = (M + 63) / 64;                 // 109
    dim3 gridQKV(12, mtiles);                   // N=768
    dim3 gridC(4, mtiles);                      // N=256
    dim3 gridAttn((N_ + 63) / 64, B_ * NH, KC);

    embed_kernel<<<dim3(N_, B_), C_>>>(x, W_pe, b_pe, cls);

    for (int i = 0; i < DEPTH; i++) {
        const float* wqkv  = Wqkv  + i * C_ * 3 * C_;
        const float* wproj = Wproj + i * C_ * C_;
        const float* w1    = W1    + i * C_ * C_;
        const float* w2    = W2    + i * C_ * C_;

        ln_kernel<<<M, C_>>>(t, y, ln1_g + i * C_, ln1_b + i * C_);
        gemm_tf32<false, false><<<gridQKV, 128>>>(y, wqkv, nullptr, qkv, M, C_, 3 * C_);
        attn_kernel<<<gridAttn, 128>>>(qkv, opart, lpart);
        attn_combine_kernel<<<M, C_>>>(opart, lpart, o);
        gemm_tf32<false, true><<<gridC, 128>>>(o, wproj, bproj + i * C_, t, M, C_, C_);
        ln_kernel<<<M, C_>>>(t, y, ln2_g + i * C_, ln2_b + i * C_);
        gemm_tf32<true, false><<<gridC, 128>>>(y, w1, b1 + i * C_, h, M, C_, C_);
        gemm_tf32<false, true><<<gridC, 128>>>(h, w2, b2 + i * C_, t, M, C_, C_);
    }

    final_ln_kernel<<<M, C_>>>(t, normf_g, normf_b, out);
}

// round 10
// speedup vs baseline: 2.5025x; 1.1001x over previous
#include <cuda_runtime.h>
#include <cuda_bf16.h>

// Problem constants
#define B_   4
#define CIN  64
#define C_   256
#define N_   1729          // 1 cls + 12*12*12 tokens
#define P_   1728
#define NH   8
#define HD   32
#define DEPTH 2
#define M_TOK (B_ * N_)    // 6916
#define KC   2             // key-split chunks
#define KCH  896           // keys per chunk (14 tiles of 64)

typedef unsigned int uint32;

// ---- bf16 helpers ----
__device__ __forceinline__ uint32 bf2(float lo, float hi) {
    __nv_bfloat162 t = __floats2bfloat162_rn(lo, hi);   // lo -> low 16 bits
    return *(uint32*)&t;
}

// bf16 m16n8k16 mma: D = A @ B^T + D  (A,B bf16, C/D fp32)
__device__ __forceinline__ void mma16816(float* c, const uint32* a, uint32 b0, uint32 b1) {
    asm volatile(
        "mma.sync.aligned.m16n8k16.row.col.f32.bf16.bf16.f32 "
        "{%0,%1,%2,%3}, {%4,%5,%6,%7}, {%8,%9}, {%0,%1,%2,%3};\n"
        : "+f"(c[0]), "+f"(c[1]), "+f"(c[2]), "+f"(c[3])
        : "r"(a[0]), "r"(a[1]), "r"(a[2]), "r"(a[3]), "r"(b0), "r"(b1));
}

// tf32 m16n8k8 mma
__device__ __forceinline__ void mma_tf32(float* c, const uint32* a, uint32 b0, uint32 b1) {
    asm volatile(
        "mma.sync.aligned.m16n8k8.row.col.f32.tf32.tf32.f32 "
        "{%0,%1,%2,%3}, {%4,%5,%6,%7}, {%8,%9}, {%0,%1,%2,%3};\n"
        : "+f"(c[0]), "+f"(c[1]), "+f"(c[2]), "+f"(c[3])
        : "r"(a[0]), "r"(a[1]), "r"(a[2]), "r"(a[3]), "r"(b0), "r"(b1));
}

__device__ __forceinline__ float cvt_tf32f(float f) {
    uint32 r; asm("cvt.rna.tf32.f32 %0, %1;" : "=r"(r) : "f"(f));
    return __uint_as_float(r);
}

__device__ __forceinline__ void ldsm4(uint32& r0, uint32& r1, uint32& r2, uint32& r3,
                                      uint32 addr) {
    asm volatile("ldmatrix.sync.aligned.m8n8.x4.shared.b16 {%0,%1,%2,%3}, [%4];"
                 : "=r"(r0), "=r"(r1), "=r"(r2), "=r"(r3) : "r"(addr));
}
__device__ __forceinline__ void ldsm4t(uint32& r0, uint32& r1, uint32& r2, uint32& r3,
                                       uint32 addr) {
    asm volatile("ldmatrix.sync.aligned.m8n8.x4.trans.shared.b16 {%0,%1,%2,%3}, [%4];"
                 : "=r"(r0), "=r"(r1), "=r"(r2), "=r"(r3) : "r"(addr));
}

// Scratch (device globals; no cudaMalloc allowed)
__device__ float g_t  [M_TOK * C_];
__device__ float g_y  [M_TOK * C_];
__device__ float g_qkv[M_TOK * 3 * C_];
__device__ float g_o  [M_TOK * C_];
__device__ float g_h  [M_TOK * C_];
__device__ float g_opart[KC * M_TOK * C_];          // unnormalized partial o
__device__ float g_lpart[KC * B_ * NH * N_];        // partial softmax sums

// ---------------------------------------------------------------------------
// Patch embed: 8 tokens per block, W_pe values reused x8 (cuts L2 traffic 8x).
// Also writes the cls row (block x == 0).
// ---------------------------------------------------------------------------
__global__ __launch_bounds__(256) void embed_kernel(const float* __restrict__ x,
                                                    const float* __restrict__ W_pe,
                                                    const float* __restrict__ b_pe,
                                                    const float* __restrict__ cls) {
    int p0 = blockIdx.x * 8;
    int b  = blockIdx.y;
    int d  = threadIdx.x;

    __shared__ float sx[CIN][8];
    // load 8 tokens x 64 channels, transposed for float4 reads
#pragma unroll
    for (int i = 0; i < 2; i++) {
        int idx = d + i * 256;     // 0..511
        int c = idx >> 3, tok = idx & 7;
        sx[c][tok] = x[(size_t)(b * CIN + c) * P_ + p0 + tok];
    }
    __syncthreads();

    float acc[8];
    float bp = b_pe[d];
#pragma unroll
    for (int t = 0; t < 8; t++) acc[t] = bp;
#pragma unroll
    for (int c = 0; c < CIN; c++) {
        float w = W_pe[c * C_ + d];
        float4 x0 = *(const float4*)&sx[c][0];
        float4 x1 = *(const float4*)&sx[c][4];
        acc[0] += x0.x * w; acc[1] += x0.y * w;
        acc[2] += x0.z * w; acc[3] += x0.w * w;
        acc[4] += x1.x * w; acc[5] += x1.y * w;
        acc[6] += x1.z * w; acc[7] += x1.w * w;
    }
#pragma unroll
    for (int t = 0; t < 8; t++)
        g_t[(size_t)(b * N_ + 1 + p0 + t) * C_ + d] = acc[t];

    if (blockIdx.x == 0) g_t[(size_t)(b * N_) * C_ + d] = cls[d];
}

// ---------------------------------------------------------------------------
// LayerNorm (256 threads per token row)
// ---------------------------------------------------------------------------
__device__ __forceinline__ float ln_value(const float* __restrict__ in, int row, int tid,
                                          const float* __restrict__ g,
                                          const float* __restrict__ bb) {
    float v = in[row * C_ + tid];
    float s = v, sq = v * v;
#pragma unroll
    for (int o = 16; o > 0; o >>= 1) {
        s  += __shfl_down_sync(0xffffffffu, s,  o);
        sq += __shfl_down_sync(0xffffffffu, sq, o);
    }
    __shared__ float rs[8], rq[8];
    int wid = tid >> 5, lid = tid & 31;
    if (lid == 0) { rs[wid] = s; rq[wid] = sq; }
    __syncthreads();
    float sum = 0.f, sumq = 0.f;
#pragma unroll
    for (int i = 0; i < 8; i++) { sum += rs[i]; sumq += rq[i]; }
    float mean = sum * (1.f / C_);
    float var  = sumq * (1.f / C_) - mean * mean;
    float inv  = rsqrtf(var + 1e-5f);
    return (v - mean) * inv * g[tid] + bb[tid];
}

__global__ void ln_kernel(const float* __restrict__ in, float* __restrict__ out,
                          const float* __restrict__ g, const float* __restrict__ bb) {
    int row = blockIdx.x;
    int tid = threadIdx.x;
    out[row * C_ + tid] = ln_value(in, row, tid, g, bb);
}

__global__ void final_ln_kernel(const float* __restrict__ in,
                                const float* __restrict__ g, const float* __restrict__ bb,
                                float* __restrict__ out) {
    int row = blockIdx.x;
    int tid = threadIdx.x;
    float val = ln_value(in, row, tid, g, bb);
    int b = row / N_, n = row % N_;
    if (n == 0) out[b * C_ + tid] = val;
    else        out[B_ * C_ + (b * C_ + tid) * P_ + (n - 1)] = val;
}

// ---------------------------------------------------------------------------
// tf32 tensor-core GEMM with register prefetch (software pipeline).
// BM=64, BN=16*NT (NT=4 -> 64 for QKV; NT=2 -> 32 for N=256 GEMMs -> 2x CTAs).
// 128 threads = 4 warps (2m x 2n); warp = 32m x (8*NT)n via m16n8k8.
// ---------------------------------------------------------------------------
template<int NT, bool GELU, bool RES>
__global__ __launch_bounds__(128) void gemm_tf32(const float* __restrict__ A,
                                                 const float* __restrict__ W,
                                                 const float* __restrict__ bias,
                                                 float* __restrict__ out,
                                                 int M, int K, int N) {
    constexpr int BN  = 16 * NT;
    constexpr int NB4 = BN / 32;            // B float4 loads per thread
    __shared__ float sA[64][20];            // [m][k], stride 20: conflict-free frags
    __shared__ float sB[16][BN + 4];        // [k][n]
    int tid  = threadIdx.x;
    int warp = tid >> 5, lane = tid & 31;
    int g = lane >> 2, qd = lane & 3;
    int wm = warp >> 1, wn = warp & 1;
    int m0 = blockIdx.y * 64;
    int n0 = blockIdx.x * BN;

    float c[2][NT][4];
#pragma unroll
    for (int mt = 0; mt < 2; mt++)
#pragma unroll
        for (int nt = 0; nt < NT; nt++)
#pragma unroll
            for (int j = 0; j < 4; j++) c[mt][nt][j] = 0.f;

    // ---- initial tile fill (k0 = 0) ----
#pragma unroll
    for (int i = 0; i < 2; i++) {
        int idx = tid + i * 128;
        int m = idx >> 2, q = idx & 3;
        int gm = m0 + m;
        float4 av = (gm < M) ? *(const float4*)(A + (size_t)gm * K + q * 4)
                             : make_float4(0.f, 0.f, 0.f, 0.f);
        av.x = cvt_tf32f(av.x); av.y = cvt_tf32f(av.y);
        av.z = cvt_tf32f(av.z); av.w = cvt_tf32f(av.w);
        *(float4*)&sA[m][q * 4] = av;
    }
#pragma unroll
    for (int i = 0; i < NB4; i++) {
        int idx = tid + i * 128;
        int kl = idx / (BN / 4), nl = (idx % (BN / 4)) * 4;
        float4 bv4 = *(const float4*)(W + (size_t)kl * N + n0 + nl);
        bv4.x = cvt_tf32f(bv4.x); bv4.y = cvt_tf32f(bv4.y);
        bv4.z = cvt_tf32f(bv4.z); bv4.w = cvt_tf32f(bv4.w);
        *(float4*)&sB[kl][nl] = bv4;
    }
    __syncthreads();

    for (int k0 = 0; k0 < K; k0 += 16) {
        // prefetch next tile into registers (overlaps with mma below)
        bool nxt = (k0 + 16) < K;
        float4 apre[2], bpre[NB4];
        if (nxt) {
#pragma unroll
            for (int i = 0; i < 2; i++) {
                int idx = tid + i * 128;
                int m = idx >> 2, q = idx & 3;
                int gm = m0 + m;
                apre[i] = (gm < M) ? *(const float4*)(A + (size_t)gm * K + k0 + 16 + q * 4)
                                   : make_float4(0.f, 0.f, 0.f, 0.f);
            }
#pragma unroll
            for (int i = 0; i < NB4; i++) {
                int idx = tid + i * 128;
                int kl = idx / (BN / 4), nl = (idx % (BN / 4)) * 4;
                bpre[i] = *(const float4*)(W + (size_t)(k0 + 16 + kl) * N + n0 + nl);
            }
        }

        // mma over current smem tile
#pragma unroll
        for (int ks = 0; ks < 2; ks++) {
            int k8 = ks * 8;
            uint32 a[2][4];
#pragma unroll
            for (int mt = 0; mt < 2; mt++) {
                int mrow = wm * 32 + mt * 16 + g;
                a[mt][0] = __float_as_uint(sA[mrow    ][qd + k8]);
                a[mt][1] = __float_as_uint(sA[mrow + 8][qd + k8]);
                a[mt][2] = __float_as_uint(sA[mrow    ][qd + 4 + k8]);
                a[mt][3] = __float_as_uint(sA[mrow + 8][qd + 4 + k8]);
            }
#pragma unroll
            for (int nt = 0; nt < NT; nt++) {
                int ncol = wn * (8 * NT) + nt * 8 + g;
                uint32 b0 = __float_as_uint(sB[qd + k8    ][ncol]);
                uint32 b1 = __float_as_uint(sB[qd + 4 + k8][ncol]);
#pragma unroll
                for (int mt = 0; mt < 2; mt++)
                    mma_tf32(c[mt][nt], a[mt], b0, b1);
            }
        }
        __syncthreads();

        if (nxt) {
#pragma unroll
            for (int i = 0; i < 2; i++) {
                int idx = tid + i * 128;
                int m = idx >> 2, q = idx & 3;
                float4 av = apre[i];
                av.x = cvt_tf32f(av.x); av.y = cvt_tf32f(av.y);
                av.z = cvt_tf32f(av.z); av.w = cvt_tf32f(av.w);
                *(float4*)&sA[m][q * 4] = av;
            }
#pragma unroll
            for (int i = 0; i < NB4; i++) {
                int idx = tid + i * 128;
                int kl = idx / (BN / 4), nl = (idx % (BN / 4)) * 4;
                float4 bv4 = bpre[i];
                bv4.x = cvt_tf32f(bv4.x); bv4.y = cvt_tf32f(bv4.y);
                bv4.z = cvt_tf32f(bv4.z); bv4.w = cvt_tf32f(bv4.w);
                *(float4*)&sB[kl][nl] = bv4;
            }
            __syncthreads();
        }
    }

    // Epilogue
#pragma unroll
    for (int nt = 0; nt < NT; nt++) {
        int col = n0 + wn * (8 * NT) + nt * 8 + 2 * qd;
        float bv0 = bias ? bias[col]     : 0.f;
        float bv1 = bias ? bias[col + 1] : 0.f;
#pragma unroll
        for (int mt = 0; mt < 2; mt++) {
            int row0 = m0 + wm * 32 + mt * 16 + g;
#pragma unroll
            for (int half = 0; half < 2; half++) {
                int row = row0 + half * 8;
                if (row >= M) continue;
                float v0 = c[mt][nt][half * 2]     + bv0;
                float v1 = c[mt][nt][half * 2 + 1] + bv1;
                if (GELU) { v0 = v0 * normcdff(v0); v1 = v1 * normcdff(v1); }
                float* op = out + (size_t)row * N + col;
                if (RES) {
                    float2 prev = *(const float2*)op;
                    *(float2*)op = make_float2(prev.x + v0, prev.y + v1);
                } else {
                    *(float2*)op = make_float2(v0, v1);
                }
            }
        }
    }
}

// ---------------------------------------------------------------------------
// bf16 tensor-core flash attention (split-K, no max-subtraction softmax).
// ldmatrix for all B fragments; V stored non-transposed, read via .trans.
// ---------------------------------------------------------------------------
__global__ __launch_bounds__(128) void attn_kernel(const float* __restrict__ qkv,
                                                   float* __restrict__ opart,
                                                   float* __restrict__ lpart) {
    int qt  = blockIdx.x;
    int bh  = blockIdx.y;
    int b   = bh >> 3;
    int h   = bh & 7;
    int kc  = blockIdx.z;
    int tid = threadIdx.x;
    int warp = tid >> 5, lane = tid & 31;
    int g = lane >> 2, qd = lane & 3;

    // 40-element rows (80 B): 16B-aligned rows, conflict-free ldmatrix
    __shared__ __align__(16) __nv_bfloat16 sK[64][40];
    __shared__ __align__(16) __nv_bfloat16 sV[64][40];
    uint32 skb = (uint32)__cvta_generic_to_shared(&sK[0][0]);
    uint32 svb = (uint32)__cvta_generic_to_shared(&sV[0][0]);
    int lrow = lane & 7, lgrp = lane >> 3;
    // K: matrices = 4 dim-blocks of one 8-key block; lanes 8g..8g+7 -> dim block g
    uint32 kaddr = skb + (uint32)(lrow * 80 + lgrp * 16);
    // V: matrices = 4 key-blocks (8 keys each) at one dim block; + nd*16 later
    uint32 vaddr = svb + (uint32)((lgrp * 8 + lrow) * 80);

    const float scale = 0.17677669529663687f;   // 1/sqrt(32)

    int rowA = qt * 64 + warp * 16 + g;
    int rowB = rowA + 8;
    int rAc = min(rowA, N_ - 1);
    int rBc = min(rowB, N_ - 1);

    uint32 qa[2][4];
    {
        const float* qA = qkv + (size_t)(b * N_ + rAc) * (3 * C_) + h * HD;
        const float* qB = qkv + (size_t)(b * N_ + rBc) * (3 * C_) + h * HD;
#pragma unroll
        for (int kk = 0; kk < 2; kk++) {
            int c0 = kk * 16 + 2 * qd;
            float2 a0 = *(const float2*)(qA + c0);
            float2 a1 = *(const float2*)(qB + c0);
            float2 a2 = *(const float2*)(qA + c0 + 8);
            float2 a3 = *(const float2*)(qB + c0 + 8);
            qa[kk][0] = bf2(a0.x * scale, a0.y * scale);
            qa[kk][1] = bf2(a1.x * scale, a1.y * scale);
            qa[kk][2] = bf2(a2.x * scale, a2.y * scale);
            qa[kk][3] = bf2(a3.x * scale, a3.y * scale);
        }
    }

    float oacc[4][4];
#pragma unroll
    for (int i = 0; i < 4; i++)
#pragma unroll
        for (int j = 0; j < 4; j++) oacc[i][j] = 0.f;
    float lA = 0.f, lB = 0.f;

    int ks = kc * KCH;
    int ke = min(N_, ks + KCH);

    for (int kb = ks; kb < ke; kb += 64) {
        // Load K/V tile (fp32 gmem -> bf16 smem, both [key][dim])
#pragma unroll
        for (int i = 0; i < 4; i++) {
            int idx = tid + i * 128;
            int key = idx >> 3;
            int d4  = idx & 7;
            int m   = kb + key;
            int mc  = min(m, N_ - 1);
            size_t base = (size_t)(b * N_ + mc) * (3 * C_) + h * HD + d4 * 4;
            float4 kv = *(const float4*)(qkv + base + C_);
            float4 vv = *(const float4*)(qkv + base + 2 * C_);
            *(uint2*)&sK[key][d4 * 4] = make_uint2(bf2(kv.x, kv.y), bf2(kv.z, kv.w));
            *(uint2*)&sV[key][d4 * 4] = make_uint2(bf2(vv.x, vv.y), bf2(vv.z, vv.w));
        }
        __syncthreads();

        // S = Q @ K^T : per ns one ldmatrix.x4 (b0/b1 for kk=0,1)
        float sacc[8][4];
#pragma unroll
        for (int ns = 0; ns < 8; ns++) {
#pragma unroll
            for (int j = 0; j < 4; j++) sacc[ns][j] = 0.f;
            uint32 b0, b1, b2, b3;
            ldsm4(b0, b1, b2, b3, kaddr + ns * 640);   // 8 rows * 80 B
            mma16816(sacc[ns], qa[0], b0, b1);
            mma16816(sacc[ns], qa[1], b2, b3);
        }

        // softmax (no max shift) + pack P as bf16 A-fragments
        uint32 pa[4][4];
#pragma unroll
        for (int ns = 0; ns < 8; ns++) {
            int cb = kb + ns * 8 + 2 * qd;
            float p0 = (cb     < N_) ? __expf(sacc[ns][0]) : 0.f;
            float p1 = (cb + 1 < N_) ? __expf(sacc[ns][1]) : 0.f;
            float p2 = (cb     < N_) ? __expf(sacc[ns][2]) : 0.f;
            float p3 = (cb + 1 < N_) ? __expf(sacc[ns][3]) : 0.f;
            lA += p0 + p1;
            lB += p2 + p3;
            int kk = ns >> 1;
            if (ns & 1) { pa[kk][2] = bf2(p0, p1); pa[kk][3] = bf2(p2, p3); }
            else        { pa[kk][0] = bf2(p0, p1); pa[kk][1] = bf2(p2, p3); }
        }

        // O += P @ V : per nd two ldmatrix.x4.trans (keys 0-31, 32-63)
#pragma unroll
        for (int nd = 0; nd < 4; nd++) {
            uint32 b0, b1, b2, b3;
            ldsm4t(b0, b1, b2, b3, vaddr + nd * 16);
            mma16816(oacc[nd], pa[0], b0, b1);
            mma16816(oacc[nd], pa[1], b2, b3);
            ldsm4t(b0, b1, b2, b3, vaddr + nd * 16 + 2560);   // +32 rows
            mma16816(oacc[nd], pa[2], b0, b1);
            mma16816(oacc[nd], pa[3], b2, b3);
        }
        __syncthreads();
    }

    lA += __shfl_xor_sync(0xffffffffu, lA, 1);
    lA += __shfl_xor_sync(0xffffffffu, lA, 2);
    lB += __shfl_xor_sync(0xffffffffu, lB, 1);
    lB += __shfl_xor_sync(0xffffffffu, lB, 2);

    size_t obase = (size_t)kc * M_TOK * C_;
    size_t lbase = (size_t)kc * B_ * NH * N_ + (size_t)bh * N_;
    if (rowA < N_) {
        float* op = opart + obase + (size_t)(b * N_ + rowA) * C_ + h * HD;
#pragma unroll
        for (int nd = 0; nd < 4; nd++)
            *(float2*)(op + nd * 8 + 2 * qd) = make_float2(oacc[nd][0], oacc[nd][1]);
        if (qd == 0) lpart[lbase + rowA] = lA;
    }
    if (rowB < N_) {
        float* op = opart + obase + (size_t)(b * N_ + rowB) * C_ + h * HD;
#pragma unroll
        for (int nd = 0; nd < 4; nd++)
            *(float2*)(op + nd * 8 + 2 * qd) = make_float2(oacc[nd][2], oacc[nd][3]);
        if (qd == 0) lpart[lbase + rowB] = lB;
    }
}

// Combine split-K partials: o = (sum_kc opart) / (sum_kc lpart)
__global__ void attn_combine_kernel(const float* __restrict__ opart,
                                    const float* __restrict__ lpart,
                                    float* __restrict__ o_out) {
    int row = blockIdx.x;
    int tid = threadIdx.x;
    int b = row / N_, n = row % N_;
    int h = tid >> 5;

    float osum = 0.f, lsum = 0.f;
#pragma unroll
    for (int kc = 0; kc < KC; kc++) {
        osum += opart[(size_t)kc * M_TOK * C_ + (size_t)row * C_ + tid];
        lsum += lpart[(size_t)kc * B_ * NH * N_ + (size_t)(b * NH + h) * N_ + n];
    }
    o_out[(size_t)row * C_ + tid] = osum / lsum;
}

// ---------------------------------------------------------------------------
// Host launch
// ---------------------------------------------------------------------------
extern "C" void kernel_launch(void* const* d_in, const int* in_sizes, int n_in,
                              void* d_out, int out_size) {
    const float* x       = (const float*)d_in[0];
    const float* W_pe    = (const float*)d_in[1];
    const float* b_pe    = (const float*)d_in[2];
    const float* cls     = (const float*)d_in[3];
    const float* ln1_g   = (const float*)d_in[4];
    const float* ln1_b   = (const float*)d_in[5];
    const float* Wqkv    = (const float*)d_in[6];
    const float* Wproj   = (const float*)d_in[7];
    const float* bproj   = (const float*)d_in[8];
    const float* ln2_g   = (const float*)d_in[9];
    const float* ln2_b   = (const float*)d_in[10];
    const float* W1      = (const float*)d_in[11];
    const float* b1      = (const float*)d_in[12];
    const float* W2      = (const float*)d_in[13];
    const float* b2      = (const float*)d_in[14];
    const float* normf_g = (const float*)d_in[15];
    const float* normf_b = (const float*)d_in[16];
    float* out = (float*)d_out;

    float *t, *y, *qkv, *o, *h, *opart, *lpart;
    cudaGetSymbolAddress((void**)&t,     g_t);
    cudaGetSymbolAddress((void**)&y,     g_y);
    cudaGetSymbolAddress((void**)&qkv,   g_qkv);
    cudaGetSymbolAddress((void**)&o,     g_o);
    cudaGetSymbolAddress((void**)&h,     g_h);
    cudaGetSymbolAddress((void**)&opart, g_opart);
    cudaGetSymbolAddress((void**)&lpart, g_lpart);

    const int M = M_TOK;
    int mtiles = (M + 63) / 64;                 // 109
    dim3 gridQKV(12, mtiles);                   // BN=64, N=768
    dim3 gridC(8, mtiles);                      // BN=32, N=256 -> 872 CTAs
    dim3 gridAttn((N_ + 63) / 64, B_ * NH, KC);

    embed_kernel<<<dim3(P_ / 8, B_), 256>>>(x, W_pe, b_pe, cls);

    for (int i = 0; i < DEPTH; i++) {
        const float* wqkv  = Wqkv  + i * C_ * 3 * C_;
        const float* wproj = Wproj + i * C_ * C_;
        const float* w1    = W1    + i * C_ * C_;
        const float* w2    = W2    + i * C_ * C_;

        ln_kernel<<<M, C_>>>(t, y, ln1_g + i * C_, ln1_b + i * C_);
        gemm_tf32<4, false, false><<<gridQKV, 128>>>(y, wqkv, nullptr, qkv, M, C_, 3 * C_);
        attn_kernel<<<gridAttn, 128>>>(qkv, opart, lpart);
        attn_combine_kernel<<<M, C_>>>(opart, lpart, o);
        gemm_tf32<2, false, true><<<gridC, 128>>>(o, wproj, bproj + i * C_, t, M, C_, C_);
        ln_kernel<<<M, C_>>>(t, y, ln2_g + i * C_, ln2_b + i * C_);
        gemm_tf32<2, true, false><<<gridC, 128>>>(y, w1, b1 + i * C_, h, M, C_, C_);
        gemm_tf32<2, false, true><<<gridC, 128>>>(h, w2, b2 + i * C_, t, M, C_, C_);
    }

    final_ln_kernel<<<M, C_>>>(t, normf_g, normf_b, out);
}